// round 5
// baseline (speedup 1.0000x reference)
#include <cuda_runtime.h>
#include <math.h>

#define B_    8
#define T_    2048
#define DIMC  512
#define NH_   8
#define NKV_  4
#define HD_   64
#define KVD_  256

// Scratch (no dynamic allocation allowed)
__device__ float g_q[B_ * T_ * DIMC];
__device__ float g_k[B_ * T_ * KVD_];
__device__ float g_v[B_ * T_ * KVD_];
__device__ float g_y[B_ * T_ * DIMC];

// ---------------------------------------------------------------------------
// Packed f32x2 helpers (sm_103a FFMA2 — ptxas never emits these from C++)
// ---------------------------------------------------------------------------
typedef unsigned long long u64t;

__device__ __forceinline__ u64t f2pack(float lo, float hi) {
    u64t r; asm("mov.b64 %0, {%1, %2};" : "=l"(r) : "f"(lo), "f"(hi)); return r;
}
__device__ __forceinline__ u64t fbcast(float x) {
    u64t r; asm("mov.b64 %0, {%1, %1};" : "=l"(r) : "f"(x)); return r;
}
__device__ __forceinline__ void f2unpack(u64t v, float& lo, float& hi) {
    asm("mov.b64 {%0, %1}, %2;" : "=f"(lo), "=f"(hi) : "l"(v));
}
__device__ __forceinline__ u64t ffma2(u64t a, u64t b, u64t c) {
    u64t d; asm("fma.rn.f32x2 %0, %1, %2, %3;" : "=l"(d) : "l"(a), "l"(b), "l"(c));
    return d;
}
__device__ __forceinline__ u64t fmul2(u64t a, u64t b) {
    u64t d; asm("mul.rn.f32x2 %0, %1, %2;" : "=l"(d) : "l"(a), "l"(b));
    return d;
}
// 16B shared load straight into two 64-bit regs (no pack MOVs)
__device__ __forceinline__ void lds_v2u64(const void* p, u64t& a, u64t& b) {
    unsigned s = (unsigned)__cvta_generic_to_shared(p);
    asm volatile("ld.shared.v2.b64 {%0, %1}, [%2];" : "=l"(a), "=l"(b) : "r"(s));
}

// ---------------------------------------------------------------------------
// GEMM: C[M,N] = A[M,K] @ W[N,K]^T   (both row-major). 64x64 tile, BK=16,
// 256 threads, 4x4 register blocking (acc held as 4x2 packed f32x2).
// ---------------------------------------------------------------------------
__global__ __launch_bounds__(256) void gemm_tn(const float* __restrict__ A,
                                               const float* __restrict__ W,
                                               float* __restrict__ C,
                                               int N, int K) {
    __shared__ float As[16][64];
    __shared__ float Ws[16][64];
    int tid = threadIdx.x;
    int m0 = blockIdx.y * 64, n0 = blockIdx.x * 64;
    int tx = tid & 15, ty = tid >> 4;
    int lrow = tid >> 2, lk = (tid & 3) * 4;

    u64t acc[4][2];
#pragma unroll
    for (int i = 0; i < 4; i++) { acc[i][0] = 0ULL; acc[i][1] = 0ULL; }

    const float* Ap  = A + (size_t)(m0 + lrow) * K + lk;
    const float* Wp_ = W + (size_t)(n0 + lrow) * K + lk;

    for (int k0 = 0; k0 < K; k0 += 16) {
        float4 av = *(const float4*)(Ap + k0);
        float4 wv = *(const float4*)(Wp_ + k0);
        As[lk + 0][lrow] = av.x; As[lk + 1][lrow] = av.y;
        As[lk + 2][lrow] = av.z; As[lk + 3][lrow] = av.w;
        Ws[lk + 0][lrow] = wv.x; Ws[lk + 1][lrow] = wv.y;
        Ws[lk + 2][lrow] = wv.z; Ws[lk + 3][lrow] = wv.w;
        __syncthreads();
#pragma unroll
        for (int k = 0; k < 16; k++) {
            float4 a = *(const float4*)&As[k][ty * 4];
            u64t wn01, wn23;
            lds_v2u64(&Ws[k][tx * 4], wn01, wn23);
            float am[4] = {a.x, a.y, a.z, a.w};
#pragma unroll
            for (int i = 0; i < 4; i++) {
                u64t am2 = fbcast(am[i]);
                acc[i][0] = ffma2(am2, wn01, acc[i][0]);
                acc[i][1] = ffma2(am2, wn23, acc[i][1]);
            }
        }
        __syncthreads();
    }
#pragma unroll
    for (int i = 0; i < 4; i++) {
        float4 r;
        f2unpack(acc[i][0], r.x, r.y);
        f2unpack(acc[i][1], r.z, r.w);
        *(float4*)(C + (size_t)(m0 + ty * 4 + i) * N + n0 + tx * 4) = r;
    }
}

// ---------------------------------------------------------------------------
// Fused per-head RMS norm + RoPE. One warp per head; lane l owns the rotation
// pair (l, l+32). grid = B*T rows, block = nh*32.
// ---------------------------------------------------------------------------
__global__ void normrope(float* __restrict__ buf, int nh) {
    int row  = blockIdx.x;            // b*T + t
    int t    = row & (T_ - 1);
    int h    = threadIdx.x >> 5;
    int lane = threadIdx.x & 31;
    float* p = buf + (size_t)row * (nh * HD_) + h * HD_;

    float x1 = p[lane];
    float x2 = p[lane + 32];
    float ss = x1 * x1 + x2 * x2;
#pragma unroll
    for (int o = 16; o; o >>= 1) ss += __shfl_xor_sync(0xffffffffu, ss, o);
    float r = rsqrtf(ss * (1.0f / 64.0f) + 1.1920928955078125e-07f);

    float inv = powf(10000.0f, -(float)(2 * lane) / 64.0f);
    float f   = (float)t * inv;
    float s   = sinf(f);
    float c   = cosf(f);

    x1 *= r; x2 *= r;
    p[lane]      = x1 * c + x2 * s;
    p[lane + 32] = -x1 * s + x2 * c;
}

// ---------------------------------------------------------------------------
// Causal flash attention, fp32 + packed f32x2. FOUR threads per query row
// (16 head-dims each) to kill register pressure: ~85 regs/thread, 512-thread
// blocks, 16 resident warps/SM. QK partial dots combined with 2 quad shuffles.
// ---------------------------------------------------------------------------
#define BM 128
#define BN 32

__global__ __launch_bounds__(512) void attn(const float* __restrict__ Q,
                                            const float* __restrict__ Kg,
                                            const float* __restrict__ Vg,
                                            float* __restrict__ Y) {
    __shared__ float Ks[BN][HD_];
    __shared__ float Vs[BN][HD_];

    int tid  = threadIdx.x;
    int row  = tid >> 2;              // 0..127 query row within block
    int part = tid & 3;               // which 16-dim slice this thread owns
    int d0   = part * 16;
    int qb = blockIdx.x, h = blockIdx.y, b = blockIdx.z;
    int m  = qb * BM + row;           // global query row
    int hk = h >> 1;                  // GQA: rep = NH/NKV = 2

    const float* qp = Q + (size_t)(b * T_ + m) * DIMC + h * HD_ + d0;
    u64t q2[8];                       // 16 dims, pre-scaled, packed
#pragma unroll
    for (int d = 0; d < 16; d += 4) {
        float4 v4 = *(const float4*)(qp + d);
        q2[d / 2 + 0] = f2pack(v4.x * 0.125f, v4.y * 0.125f);
        q2[d / 2 + 1] = f2pack(v4.z * 0.125f, v4.w * 0.125f);
    }
    u64t o2[8];
#pragma unroll
    for (int d = 0; d < 8; d++) o2[d] = 0ULL;
    float mi = -INFINITY, l = 0.f;

    // cooperative load indices: thread loads one K float4 and one V float4
    int lj = tid >> 4;                // 0..31 row in tile
    int ld4 = (tid & 15) << 2;        // 0..60 dim offset

    int kend = qb * BM + BM;          // exclusive causal bound for this block
    for (int k0 = 0; k0 < kend; k0 += BN) {
        size_t gb = (size_t)(b * T_ + k0 + lj) * KVD_ + hk * HD_ + ld4;
        *(float4*)&Ks[lj][ld4] = *(const float4*)(Kg + gb);
        *(float4*)&Vs[lj][ld4] = *(const float4*)(Vg + gb);
        __syncthreads();

        float s[BN];
#pragma unroll
        for (int j = 0; j < BN; j++) {
            u64t acc2 = 0ULL;
#pragma unroll
            for (int d = 0; d < 16; d += 4) {
                u64t k01, k23;
                lds_v2u64(&Ks[j][d0 + d], k01, k23);
                acc2 = ffma2(q2[d / 2 + 0], k01, acc2);
                acc2 = ffma2(q2[d / 2 + 1], k23, acc2);
            }
            float alo, ahi;
            f2unpack(acc2, alo, ahi);
            float acc = alo + ahi;
            // combine partials across the quad (lanes row*4 .. row*4+3)
            acc += __shfl_xor_sync(0xffffffffu, acc, 1);
            acc += __shfl_xor_sync(0xffffffffu, acc, 2);
            s[j] = (k0 + j <= m) ? acc : -INFINITY;
        }

        float tmax = -INFINITY;
#pragma unroll
        for (int j = 0; j < BN; j++) tmax = fmaxf(tmax, s[j]);
        float mnew = fmaxf(mi, tmax);
        float corr = __expf(mi - mnew);       // 0 on first live tile
        float psum = 0.f;
#pragma unroll
        for (int j = 0; j < BN; j++) {
            float pj = __expf(s[j] - mnew);   // exp(-inf)=0 handles mask
            s[j] = pj;
            psum += pj;
        }
        l = l * corr + psum;
        u64t corr2 = fbcast(corr);
#pragma unroll
        for (int d = 0; d < 8; d++) o2[d] = fmul2(corr2, o2[d]);
#pragma unroll
        for (int j = 0; j < BN; j++) {
            u64t pj2 = fbcast(s[j]);
#pragma unroll
            for (int d = 0; d < 16; d += 4) {
                u64t v01, v23;
                lds_v2u64(&Vs[j][d0 + d], v01, v23);
                o2[d / 2 + 0] = ffma2(pj2, v01, o2[d / 2 + 0]);
                o2[d / 2 + 1] = ffma2(pj2, v23, o2[d / 2 + 1]);
            }
        }
        mi = mnew;
        __syncthreads();
    }

    float invl = 1.f / l;
    float* yp = Y + (size_t)(b * T_ + m) * DIMC + h * HD_ + d0;  // [B,T,H*D]
#pragma unroll
    for (int d = 0; d < 16; d += 4) {
        float4 r;
        f2unpack(o2[d / 2 + 0], r.x, r.y);
        f2unpack(o2[d / 2 + 1], r.z, r.w);
        r.x *= invl; r.y *= invl; r.z *= invl; r.w *= invl;
        *(float4*)(yp + d) = r;
    }
}

// ---------------------------------------------------------------------------
extern "C" void kernel_launch(void* const* d_in, const int* in_sizes, int n_in,
                              void* d_out, int out_size) {
    const float* x  = (const float*)d_in[0];
    const float* Wq = (const float*)d_in[1];
    const float* Wk = (const float*)d_in[2];
    const float* Wv = (const float*)d_in[3];
    const float* Wp = (const float*)d_in[4];
    float* out = (float*)d_out;

    float *q, *k, *v, *y;
    cudaGetSymbolAddress((void**)&q, g_q);
    cudaGetSymbolAddress((void**)&k, g_k);
    cudaGetSymbolAddress((void**)&v, g_v);
    cudaGetSymbolAddress((void**)&y, g_y);

    const int M = B_ * T_;                       // 16384
    dim3 gq(DIMC / 64, M / 64);                  // 8 x 256
    dim3 gkv(KVD_ / 64, M / 64);                 // 4 x 256

    gemm_tn<<<gq,  256>>>(x, Wq, q, DIMC, DIMC);
    gemm_tn<<<gkv, 256>>>(x, Wk, k, KVD_, DIMC);
    gemm_tn<<<gkv, 256>>>(x, Wv, v, KVD_, DIMC);

    normrope<<<M, NH_  * 32>>>(q, NH_);
    normrope<<<M, NKV_ * 32>>>(k, NKV_);

    attn<<<dim3(T_ / BM, NH_, B_), 512>>>(q, k, v, y);

    gemm_tn<<<gq, 256>>>(y, Wp, out, DIMC, DIMC);
}

// round 7
// speedup vs baseline: 2.9084x; 2.9084x over previous
#include <cuda_runtime.h>
#include <math.h>

#define B_    8
#define T_    2048
#define DIMC  512
#define NH_   8
#define NKV_  4
#define HD_   64
#define KVD_  256

// Scratch (no dynamic allocation allowed)
__device__ float g_q[B_ * T_ * DIMC];
__device__ float g_k[B_ * T_ * KVD_];
__device__ float g_v[B_ * T_ * KVD_];
__device__ float g_y[B_ * T_ * DIMC];

// ---------------------------------------------------------------------------
// Packed f32x2 helpers (sm_103a FFMA2 — ptxas never emits these from C++)
// ---------------------------------------------------------------------------
typedef unsigned long long u64t;

__device__ __forceinline__ u64t f2pack(float lo, float hi) {
    u64t r; asm("mov.b64 %0, {%1, %2};" : "=l"(r) : "f"(lo), "f"(hi)); return r;
}
__device__ __forceinline__ u64t fbcast(float x) {
    u64t r; asm("mov.b64 %0, {%1, %1};" : "=l"(r) : "f"(x)); return r;
}
__device__ __forceinline__ void f2unpack(u64t v, float& lo, float& hi) {
    asm("mov.b64 {%0, %1}, %2;" : "=f"(lo), "=f"(hi) : "l"(v));
}
__device__ __forceinline__ u64t ffma2(u64t a, u64t b, u64t c) {
    u64t d; asm("fma.rn.f32x2 %0, %1, %2, %3;" : "=l"(d) : "l"(a), "l"(b), "l"(c));
    return d;
}
__device__ __forceinline__ u64t fmul2(u64t a, u64t b) {
    u64t d; asm("mul.rn.f32x2 %0, %1, %2;" : "=l"(d) : "l"(a), "l"(b));
    return d;
}
// 16B shared load straight into two 64-bit regs (no pack MOVs)
__device__ __forceinline__ void lds_v2u64(const void* p, u64t& a, u64t& b) {
    unsigned s = (unsigned)__cvta_generic_to_shared(p);
    asm volatile("ld.shared.v2.b64 {%0, %1}, [%2];" : "=l"(a), "=l"(b) : "r"(s));
}

// ---------------------------------------------------------------------------
// GEMM: C[M,N] = A[M,K] @ W[N,K]^T   (both row-major). 64x64 tile, BK=16,
// 256 threads, 4x4 register blocking (acc held as 4x2 packed f32x2).
// SMEM rows padded to 68 floats: keeps 16B alignment for v2.b64 reads and
// reduces STS bank conflicts from 4-way to 2-way.
// ---------------------------------------------------------------------------
__global__ __launch_bounds__(256) void gemm_tn(const float* __restrict__ A,
                                               const float* __restrict__ W,
                                               float* __restrict__ C,
                                               int N, int K) {
    __shared__ float As[16][68];
    __shared__ float Ws[16][68];
    int tid = threadIdx.x;
    int m0 = blockIdx.y * 64, n0 = blockIdx.x * 64;
    int tx = tid & 15, ty = tid >> 4;
    int lrow = tid >> 2, lk = (tid & 3) * 4;

    u64t acc[4][2];
#pragma unroll
    for (int i = 0; i < 4; i++) { acc[i][0] = 0ULL; acc[i][1] = 0ULL; }

    const float* Ap  = A + (size_t)(m0 + lrow) * K + lk;
    const float* Wp_ = W + (size_t)(n0 + lrow) * K + lk;

    for (int k0 = 0; k0 < K; k0 += 16) {
        float4 av = *(const float4*)(Ap + k0);
        float4 wv = *(const float4*)(Wp_ + k0);
        As[lk + 0][lrow] = av.x; As[lk + 1][lrow] = av.y;
        As[lk + 2][lrow] = av.z; As[lk + 3][lrow] = av.w;
        Ws[lk + 0][lrow] = wv.x; Ws[lk + 1][lrow] = wv.y;
        Ws[lk + 2][lrow] = wv.z; Ws[lk + 3][lrow] = wv.w;
        __syncthreads();
#pragma unroll
        for (int k = 0; k < 16; k++) {
            float4 a = *(const float4*)&As[k][ty * 4];
            u64t wn01, wn23;
            lds_v2u64(&Ws[k][tx * 4], wn01, wn23);
            float am[4] = {a.x, a.y, a.z, a.w};
#pragma unroll
            for (int i = 0; i < 4; i++) {
                u64t am2 = fbcast(am[i]);
                acc[i][0] = ffma2(am2, wn01, acc[i][0]);
                acc[i][1] = ffma2(am2, wn23, acc[i][1]);
            }
        }
        __syncthreads();
    }
#pragma unroll
    for (int i = 0; i < 4; i++) {
        float4 r;
        f2unpack(acc[i][0], r.x, r.y);
        f2unpack(acc[i][1], r.z, r.w);
        *(float4*)(C + (size_t)(m0 + ty * 4 + i) * N + n0 + tx * 4) = r;
    }
}

// ---------------------------------------------------------------------------
// Fused per-head RMS norm + RoPE. One warp per head; lane l owns the rotation
// pair (l, l+32). grid = B*T rows, block = nh*32.
// ---------------------------------------------------------------------------
__global__ void normrope(float* __restrict__ buf, int nh) {
    int row  = blockIdx.x;            // b*T + t
    int t    = row & (T_ - 1);
    int h    = threadIdx.x >> 5;
    int lane = threadIdx.x & 31;
    float* p = buf + (size_t)row * (nh * HD_) + h * HD_;

    float x1 = p[lane];
    float x2 = p[lane + 32];
    float ss = x1 * x1 + x2 * x2;
#pragma unroll
    for (int o = 16; o; o >>= 1) ss += __shfl_xor_sync(0xffffffffu, ss, o);
    float r = rsqrtf(ss * (1.0f / 64.0f) + 1.1920928955078125e-07f);

    float inv = powf(10000.0f, -(float)(2 * lane) / 64.0f);
    float f   = (float)t * inv;
    float s   = sinf(f);
    float c   = cosf(f);

    x1 *= r; x2 *= r;
    p[lane]      = x1 * c + x2 * s;
    p[lane + 32] = -x1 * s + x2 * c;
}

// ---------------------------------------------------------------------------
// Causal flash attention, 2D-register-tiled, packed f32x2.
// Block = 256 threads (16x16). BM=64 queries, BN=32 keys per tile, HD=64.
// GEMM1: S frag [4 rows x 2 keys(tx, tx+16)].  Softmax: exact (no thread
// replication), 8 shuffles/row.  GEMM2 via P in SMEM: O frag [4 rows x 4 dims].
// ~80 regs, 44KB SMEM -> 3 blocks/SM (24 warps).
// ---------------------------------------------------------------------------
__global__ __launch_bounds__(256) void attn(const float* __restrict__ Q,
                                            const float* __restrict__ Kg,
                                            const float* __restrict__ Vg,
                                            float* __restrict__ Y) {
    __shared__ float Qs[64][68];
    __shared__ float Ks[32][68];
    __shared__ float Vs[32][68];
    __shared__ float Ps[64][36];

    int tid = threadIdx.x;
    int tx = tid & 15, ty = tid >> 4;
    int qblk = blockIdx.x, h = blockIdx.y, b = blockIdx.z;
    int m0 = qblk * 64;
    int hk = h >> 1;                  // GQA: rep = NH/NKV = 2

    // Q tile load (64x64), pre-scaled by 1/sqrt(HD)=0.125
#pragma unroll
    for (int i = 0; i < 4; i++) {
        int e = tid + 256 * i;        // 0..1023
        int r = e >> 4;
        int d4 = (e & 15) << 2;
        float4 v4 = *(const float4*)(Q + (size_t)(b * T_ + m0 + r) * DIMC + h * HD_ + d4);
        v4.x *= 0.125f; v4.y *= 0.125f; v4.z *= 0.125f; v4.w *= 0.125f;
        *(float4*)&Qs[r][d4] = v4;    // row stride 272B = 16B-aligned
    }

    u64t o2[4][2];
    float mi[4], li[4];
#pragma unroll
    for (int i = 0; i < 4; i++) {
        o2[i][0] = 0ULL; o2[i][1] = 0ULL;
        mi[i] = -INFINITY; li[i] = 0.f;
    }
    __syncthreads();

    for (int k0 = 0; k0 < m0 + 64; k0 += 32) {
        // K/V tile load (32x64 each)
#pragma unroll
        for (int i = 0; i < 2; i++) {
            int e = tid + 256 * i;    // 0..511
            int r = e >> 4;
            int d4 = (e & 15) << 2;
            size_t gb = (size_t)(b * T_ + k0 + r) * KVD_ + hk * HD_ + d4;
            *(float4*)&Ks[r][d4] = *(const float4*)(Kg + gb);
            *(float4*)&Vs[r][d4] = *(const float4*)(Vg + gb);
        }
        __syncthreads();

        // ---- GEMM1: S = Qs @ Ks^T, fragment [4 rows x keys {tx, tx+16}]
        u64t acc2[4][2];
#pragma unroll
        for (int i = 0; i < 4; i++) { acc2[i][0] = 0ULL; acc2[i][1] = 0ULL; }
#pragma unroll
        for (int d = 0; d < 64; d += 4) {
            u64t ka0, ka1, kb0, kb1;
            lds_v2u64(&Ks[tx][d],      ka0, ka1);
            lds_v2u64(&Ks[tx + 16][d], kb0, kb1);
#pragma unroll
            for (int i = 0; i < 4; i++) {
                u64t q01, q23;
                lds_v2u64(&Qs[ty * 4 + i][d], q01, q23);
                acc2[i][0] = ffma2(q01, ka0, acc2[i][0]);
                acc2[i][0] = ffma2(q23, ka1, acc2[i][0]);
                acc2[i][1] = ffma2(q01, kb0, acc2[i][1]);
                acc2[i][1] = ffma2(q23, kb1, acc2[i][1]);
            }
        }

        // unpack + causal mask
        float sv[4][2];
#pragma unroll
        for (int i = 0; i < 4; i++) {
            int mg = m0 + ty * 4 + i;
#pragma unroll
            for (int j = 0; j < 2; j++) {
                float lo, hi; f2unpack(acc2[i][j], lo, hi);
                float s = lo + hi;
                int kg = k0 + tx + 16 * j;
                sv[i][j] = (kg <= mg) ? s : -INFINITY;
            }
        }

        // ---- online softmax (exact; reductions across the 16 tx lanes)
#pragma unroll
        for (int i = 0; i < 4; i++) {
            float rm = fmaxf(sv[i][0], sv[i][1]);
            rm = fmaxf(rm, __shfl_xor_sync(0xffffffffu, rm, 1));
            rm = fmaxf(rm, __shfl_xor_sync(0xffffffffu, rm, 2));
            rm = fmaxf(rm, __shfl_xor_sync(0xffffffffu, rm, 4));
            rm = fmaxf(rm, __shfl_xor_sync(0xffffffffu, rm, 8));
            float mnew = fmaxf(mi[i], rm);
            float corr = __expf(mi[i] - mnew);
            float p0 = __expf(sv[i][0] - mnew);   // exp(-inf)=0 handles mask
            float p1 = __expf(sv[i][1] - mnew);
            float rs = p0 + p1;
            rs += __shfl_xor_sync(0xffffffffu, rs, 1);
            rs += __shfl_xor_sync(0xffffffffu, rs, 2);
            rs += __shfl_xor_sync(0xffffffffu, rs, 4);
            rs += __shfl_xor_sync(0xffffffffu, rs, 8);
            li[i] = li[i] * corr + rs;
            u64t c2 = fbcast(corr);
            o2[i][0] = fmul2(c2, o2[i][0]);
            o2[i][1] = fmul2(c2, o2[i][1]);
            Ps[ty * 4 + i][tx]      = p0;
            Ps[ty * 4 + i][tx + 16] = p1;
            mi[i] = mnew;
        }
        __syncthreads();

        // ---- GEMM2: O += P @ Vs, fragment [4 rows x dims tx*4..tx*4+3]
#pragma unroll
        for (int k = 0; k < 32; k += 4) {
            u64t v01[4], v23[4];
#pragma unroll
            for (int kk = 0; kk < 4; kk++)
                lds_v2u64(&Vs[k + kk][tx * 4], v01[kk], v23[kk]);
#pragma unroll
            for (int i = 0; i < 4; i++) {
                int r = ty * 4 + i;
#pragma unroll
                for (int kk = 0; kk < 4; kk++) {
                    u64t p2 = fbcast(Ps[r][k + kk]);
                    o2[i][0] = ffma2(p2, v01[kk], o2[i][0]);
                    o2[i][1] = ffma2(p2, v23[kk], o2[i][1]);
                }
            }
        }
        __syncthreads();
    }

    // epilogue: normalize and store directly in [B,T,H*D]
#pragma unroll
    for (int i = 0; i < 4; i++) {
        float invl = 1.f / li[i];
        float4 r;
        f2unpack(o2[i][0], r.x, r.y);
        f2unpack(o2[i][1], r.z, r.w);
        r.x *= invl; r.y *= invl; r.z *= invl; r.w *= invl;
        int mg = m0 + ty * 4 + i;
        *(float4*)(Y + (size_t)(b * T_ + mg) * DIMC + h * HD_ + tx * 4) = r;
    }
}

// ---------------------------------------------------------------------------
extern "C" void kernel_launch(void* const* d_in, const int* in_sizes, int n_in,
                              void* d_out, int out_size) {
    const float* x  = (const float*)d_in[0];
    const float* Wq = (const float*)d_in[1];
    const float* Wk = (const float*)d_in[2];
    const float* Wv = (const float*)d_in[3];
    const float* Wp = (const float*)d_in[4];
    float* out = (float*)d_out;

    float *q, *k, *v, *y;
    cudaGetSymbolAddress((void**)&q, g_q);
    cudaGetSymbolAddress((void**)&k, g_k);
    cudaGetSymbolAddress((void**)&v, g_v);
    cudaGetSymbolAddress((void**)&y, g_y);

    const int M = B_ * T_;                       // 16384
    dim3 gq(DIMC / 64, M / 64);                  // 8 x 256
    dim3 gkv(KVD_ / 64, M / 64);                 // 4 x 256

    gemm_tn<<<gq,  256>>>(x, Wq, q, DIMC, DIMC);
    gemm_tn<<<gkv, 256>>>(x, Wk, k, KVD_, DIMC);
    gemm_tn<<<gkv, 256>>>(x, Wv, v, KVD_, DIMC);

    normrope<<<M, NH_  * 32>>>(q, NH_);
    normrope<<<M, NKV_ * 32>>>(k, NKV_);

    attn<<<dim3(T_ / 64, NH_, B_), 256>>>(q, k, v, y);

    gemm_tn<<<gq, 256>>>(y, Wp, out, DIMC, DIMC);
}